// round 3
// baseline (speedup 1.0000x reference)
#include <cuda_runtime.h>

#define N_NODES 100000
#define N_EDGES 1600000
#define D 128
#define ALPHA 0.01f
#define BN_EPS 1e-5f

// ---------------- scratch (device globals: no allocation allowed) -------------
__device__ int   g_is64;                        // 1 if edge_idx is int64, else int32
__device__ int   g_deg[N_NODES];                // in-degree per dst
__device__ int   g_rowptr[N_NODES + 1];         // CSR row pointers
__device__ int   g_cursor[N_NODES];             // fill cursors
__device__ int   g_csr[N_EDGES];                // src ids grouped by dst
__device__ float g_agg[(size_t)N_NODES * D];    // mean-aggregated features
__device__ float g_h[(size_t)N_NODES * D];      // pre-BN activations
__device__ float g_sum[D];                      // per-channel sum of h
__device__ float g_sumsq[D];                    // per-channel sum of h^2
__device__ float g_scale[D];                    // gamma * rstd
__device__ float g_shift[D];                    // beta - mu * scale

// ---------------- kernel 0: detect edge dtype --------------------------------
// int64 edges (values < 2^31): every odd int32 word is 0.
// int32 edges: odd words are src[1],src[3],... (random); all-zero is impossible.
__global__ void detect_kernel(const int* __restrict__ ei32) {
    __shared__ int flag;
    if (threadIdx.x == 0) flag = 0;
    __syncthreads();
    int v = ei32[2 * threadIdx.x + 1];   // first 512 int32 words, in bounds either way
    if (v != 0) flag = 1;
    __syncthreads();
    if (threadIdx.x == 0) g_is64 = (flag == 0) ? 1 : 0;
}

__device__ __forceinline__ int load_idx(const void* ei, int is64, int i) {
    return is64 ? (int)((const long long*)ei)[i] : ((const int*)ei)[i];
}

// ---------------- kernel 1: zero counters ------------------------------------
__global__ void zero_kernel() {
    int i = blockIdx.x * blockDim.x + threadIdx.x;
    if (i < N_NODES) g_deg[i] = 0;
    if (i < D) { g_sum[i] = 0.f; g_sumsq[i] = 0.f; }
}

// ---------------- kernel 2: count in-degree ----------------------------------
__global__ void count_kernel(const void* __restrict__ ei) {
    int e = blockIdx.x * blockDim.x + threadIdx.x;
    if (e >= N_EDGES) return;
    int is64 = g_is64;
    int dst = load_idx(ei, is64, N_EDGES + e);
    atomicAdd(&g_deg[dst], 1);
}

// ---------------- kernel 3: exclusive scan (single block) --------------------
__global__ __launch_bounds__(1024) void scan_kernel() {
    __shared__ int part[1024];
    const int t = threadIdx.x;
    const int CH = (N_NODES + 1023) / 1024;  // 98
    const int beg = t * CH;
    int s = 0;
    for (int i = 0; i < CH; i++) {
        int idx = beg + i;
        if (idx < N_NODES) s += g_deg[idx];
    }
    part[t] = s;
    __syncthreads();
    for (int off = 1; off < 1024; off <<= 1) {
        int v = (t >= off) ? part[t - off] : 0;
        __syncthreads();
        part[t] += v;
        __syncthreads();
    }
    int run = (t == 0) ? 0 : part[t - 1];
    for (int i = 0; i < CH; i++) {
        int idx = beg + i;
        if (idx < N_NODES) {
            g_rowptr[idx] = run;
            g_cursor[idx] = run;
            run += g_deg[idx];
        }
    }
    if (t == 1023) g_rowptr[N_NODES] = run;   // == N_EDGES
}

// ---------------- kernel 4: fill CSR ------------------------------------------
__global__ void fill_kernel(const void* __restrict__ ei) {
    int e = blockIdx.x * blockDim.x + threadIdx.x;
    if (e >= N_EDGES) return;
    int is64 = g_is64;
    int src = load_idx(ei, is64, e);
    int dst = load_idx(ei, is64, N_EDGES + e);
    int pos = atomicAdd(&g_cursor[dst], 1);
    g_csr[pos] = src;
}

// ---------------- kernel 5: gather + mean (one warp per node) ----------------
__global__ __launch_bounds__(256) void gather_kernel(const float* __restrict__ x) {
    int warp = (blockIdx.x * blockDim.x + threadIdx.x) >> 5;
    int lane = threadIdx.x & 31;
    if (warp >= N_NODES) return;
    int beg = g_rowptr[warp];
    int end = g_rowptr[warp + 1];
    const float4* x4 = (const float4*)x;
    float4 acc = make_float4(0.f, 0.f, 0.f, 0.f);
    float4 acc2 = make_float4(0.f, 0.f, 0.f, 0.f);
    int j = beg;
    for (; j + 1 < end; j += 2) {
        int s0 = g_csr[j];
        int s1 = g_csr[j + 1];
        float4 v0 = __ldg(x4 + (size_t)s0 * (D / 4) + lane);
        float4 v1 = __ldg(x4 + (size_t)s1 * (D / 4) + lane);
        acc.x += v0.x; acc.y += v0.y; acc.z += v0.z; acc.w += v0.w;
        acc2.x += v1.x; acc2.y += v1.y; acc2.z += v1.z; acc2.w += v1.w;
    }
    if (j < end) {
        int s0 = g_csr[j];
        float4 v0 = __ldg(x4 + (size_t)s0 * (D / 4) + lane);
        acc.x += v0.x; acc.y += v0.y; acc.z += v0.z; acc.w += v0.w;
    }
    float inv = 1.0f / (float)max(end - beg, 1);
    acc.x = (acc.x + acc2.x) * inv;
    acc.y = (acc.y + acc2.y) * inv;
    acc.z = (acc.z + acc2.z) * inv;
    acc.w = (acc.w + acc2.w) * inv;
    ((float4*)g_agg)[(size_t)warp * (D / 4) + lane] = acc;
}

// ---------------- kernel 6: fused dual GEMM + BN stats -----------------------
// h = mean @ Wl^T + bl + x @ Wr^T ; accumulate per-channel sum / sumsq.
#define BM 128
#define BN_T 128
#define BK 16

__global__ __launch_bounds__(256) void gemm_kernel(const float* __restrict__ x,
                                                   const float* __restrict__ Wl,
                                                   const float* __restrict__ bl,
                                                   const float* __restrict__ Wr) {
    __shared__ float As[BK][BM + 4];
    __shared__ float Bs[BK][BN_T + 4];
    __shared__ float s_sum[BN_T];
    __shared__ float s_sq[BN_T];

    const int tid = threadIdx.x;
    const int tx = tid & 15;
    const int ty = tid >> 4;
    const int blockRow = blockIdx.x * BM;

    float acc[8][8];
#pragma unroll
    for (int i = 0; i < 8; i++)
#pragma unroll
        for (int j = 0; j < 8; j++) acc[i][j] = 0.f;

    const int lr = tid >> 1;
    const int lc = (tid & 1) * 8;

    for (int phase = 0; phase < 2; ++phase) {
        const float* A = phase ? x : (const float*)g_agg;
        const float* W = phase ? Wr : Wl;
        for (int kb = 0; kb < D; kb += BK) {
            {
                int grow = blockRow + lr;
                float4 a0 = make_float4(0.f, 0.f, 0.f, 0.f), a1 = a0;
                if (grow < N_NODES) {
                    const float* ap = A + (size_t)grow * D + kb + lc;
                    a0 = *(const float4*)ap;
                    a1 = *(const float4*)(ap + 4);
                }
                As[lc + 0][lr] = a0.x; As[lc + 1][lr] = a0.y;
                As[lc + 2][lr] = a0.z; As[lc + 3][lr] = a0.w;
                As[lc + 4][lr] = a1.x; As[lc + 5][lr] = a1.y;
                As[lc + 6][lr] = a1.z; As[lc + 7][lr] = a1.w;
            }
            {
                const float* wp = W + lr * D + kb + lc;
                float4 b0 = *(const float4*)wp;
                float4 b1 = *(const float4*)(wp + 4);
                Bs[lc + 0][lr] = b0.x; Bs[lc + 1][lr] = b0.y;
                Bs[lc + 2][lr] = b0.z; Bs[lc + 3][lr] = b0.w;
                Bs[lc + 4][lr] = b1.x; Bs[lc + 5][lr] = b1.y;
                Bs[lc + 6][lr] = b1.z; Bs[lc + 7][lr] = b1.w;
            }
            __syncthreads();
#pragma unroll
            for (int k = 0; k < BK; ++k) {
                float a[8], b[8];
#pragma unroll
                for (int i = 0; i < 8; i++) a[i] = As[k][ty * 8 + i];
                float4 b0 = *(const float4*)&Bs[k][tx * 8];
                float4 b1 = *(const float4*)&Bs[k][tx * 8 + 4];
                b[0] = b0.x; b[1] = b0.y; b[2] = b0.z; b[3] = b0.w;
                b[4] = b1.x; b[5] = b1.y; b[6] = b1.z; b[7] = b1.w;
#pragma unroll
                for (int i = 0; i < 8; i++)
#pragma unroll
                    for (int j = 0; j < 8; j++) acc[i][j] += a[i] * b[j];
            }
            __syncthreads();
        }
    }

    float4 bias0 = *(const float4*)(bl + tx * 8);
    float4 bias1 = *(const float4*)(bl + tx * 8 + 4);
    float bsv[8] = {bias0.x, bias0.y, bias0.z, bias0.w,
                    bias1.x, bias1.y, bias1.z, bias1.w};

    if (tid < BN_T) { s_sum[tid] = 0.f; s_sq[tid] = 0.f; }
    __syncthreads();

    float lsum[8], lsq[8];
#pragma unroll
    for (int j = 0; j < 8; j++) { lsum[j] = 0.f; lsq[j] = 0.f; }

#pragma unroll
    for (int i = 0; i < 8; i++) {
        int row = blockRow + ty * 8 + i;
        if (row < N_NODES) {
            float v[8];
#pragma unroll
            for (int j = 0; j < 8; j++) {
                v[j] = acc[i][j] + bsv[j];
                lsum[j] += v[j];
                lsq[j] += v[j] * v[j];
            }
            float* hp = g_h + (size_t)row * D + tx * 8;
            *(float4*)hp       = make_float4(v[0], v[1], v[2], v[3]);
            *(float4*)(hp + 4) = make_float4(v[4], v[5], v[6], v[7]);
        }
    }
#pragma unroll
    for (int j = 0; j < 8; j++) {
        atomicAdd(&s_sum[tx * 8 + j], lsum[j]);
        atomicAdd(&s_sq[tx * 8 + j], lsq[j]);
    }
    __syncthreads();
    if (tid < BN_T) {
        atomicAdd(&g_sum[tid], s_sum[tid]);
        atomicAdd(&g_sumsq[tid], s_sq[tid]);
    }
}

// ---------------- kernel 7: finalize BN stats --------------------------------
__global__ void stats_kernel(const float* __restrict__ gamma,
                             const float* __restrict__ beta) {
    int c = threadIdx.x;
    if (c >= D) return;
    float s = g_sum[c], ss = g_sumsq[c];
    float inv_n = 1.0f / (float)N_NODES;
    float mu = s * inv_n;
    float var = ss * inv_n - mu * mu;
    float rstd = rsqrtf(var + BN_EPS);
    float sc = gamma[c] * rstd;
    g_scale[c] = sc;
    g_shift[c] = beta[c] - mu * sc;
}

// ---------------- kernel 8: normalize + LeakyReLU ----------------------------
__global__ void norm_kernel(float* __restrict__ out) {
    int i = blockIdx.x * blockDim.x + threadIdx.x;
    if (i >= N_NODES * (D / 4)) return;
    int cb = (i & 31) * 4;
    float4 sc = *(const float4*)&g_scale[cb];
    float4 sh = *(const float4*)&g_shift[cb];
    float4 v = ((float4*)g_h)[i];
    v.x = v.x * sc.x + sh.x;
    v.y = v.y * sc.y + sh.y;
    v.z = v.z * sc.z + sh.z;
    v.w = v.w * sc.w + sh.w;
    v.x = v.x >= 0.f ? v.x : ALPHA * v.x;
    v.y = v.y >= 0.f ? v.y : ALPHA * v.y;
    v.z = v.z >= 0.f ? v.z : ALPHA * v.z;
    v.w = v.w >= 0.f ? v.w : ALPHA * v.w;
    ((float4*)out)[i] = v;
}

// ---------------- launch ------------------------------------------------------
extern "C" void kernel_launch(void* const* d_in, const int* in_sizes, int n_in,
                              void* d_out, int out_size) {
    const float* x     = (const float*)d_in[0];
    const void*  ei    = d_in[1];
    const float* Wl    = (const float*)d_in[2];
    const float* bl    = (const float*)d_in[3];
    const float* Wr    = (const float*)d_in[4];
    const float* gamma = (const float*)d_in[5];
    const float* beta  = (const float*)d_in[6];
    float*       out   = (float*)d_out;

    const int elem4 = N_NODES * (D / 4);

    detect_kernel<<<1, 256>>>((const int*)ei);
    zero_kernel<<<(N_NODES + 255) / 256, 256>>>();
    count_kernel<<<(N_EDGES + 255) / 256, 256>>>(ei);
    scan_kernel<<<1, 1024>>>();
    fill_kernel<<<(N_EDGES + 255) / 256, 256>>>(ei);
    gather_kernel<<<(N_NODES * 32 + 255) / 256, 256>>>(x);
    gemm_kernel<<<(N_NODES + BM - 1) / BM, 256>>>(x, Wl, bl, Wr);
    stats_kernel<<<1, 128>>>(gamma, beta);
    norm_kernel<<<(elem4 + 255) / 256, 256>>>(out);
}

// round 4
// speedup vs baseline: 1.4908x; 1.4908x over previous
#include <cuda_runtime.h>

#define N_NODES 100000
#define N_EDGES 1600000
#define D 128
#define ALPHA 0.01f
#define BN_EPS 1e-5f

#define SCAN_CHUNK 512
#define NB_SCAN ((N_NODES + SCAN_CHUNK - 1) / SCAN_CHUNK)   // 196

// ---------------- scratch (device globals: no allocation allowed) -------------
__device__ int   g_is64;                        // 1 if edge_idx is int64, else int32
__device__ int   g_deg[N_NODES];                // in-degree per dst
__device__ int   g_rowptr[N_NODES + 1];         // CSR row pointers
__device__ int   g_cursor[N_NODES];             // fill cursors
__device__ int   g_csr[N_EDGES];                // src ids grouped by dst
__device__ int   g_bsum[NB_SCAN];               // per-block degree sums
__device__ int   g_boff[NB_SCAN];               // exclusive block offsets
__device__ float g_agg[(size_t)N_NODES * D];    // mean-aggregated features
__device__ float g_h[(size_t)N_NODES * D];      // pre-BN activations
__device__ float g_sum[D];                      // per-channel sum of h
__device__ float g_sumsq[D];                    // per-channel sum of h^2
__device__ float g_scale[D];                    // gamma * rstd
__device__ float g_shift[D];                    // beta - mu * scale

// ---------------- kernel 0: detect edge dtype --------------------------------
// int64 edges (values < 2^31): every odd int32 word is 0.
// int32 edges: odd words are src[1],src[3],... (random); all-zero is impossible.
__global__ void detect_kernel(const int* __restrict__ ei32) {
    __shared__ int flag;
    if (threadIdx.x == 0) flag = 0;
    __syncthreads();
    int v = ei32[2 * threadIdx.x + 1];
    if (v != 0) flag = 1;
    __syncthreads();
    if (threadIdx.x == 0) g_is64 = (flag == 0) ? 1 : 0;
}

__device__ __forceinline__ int load_idx(const void* ei, int is64, int i) {
    return is64 ? (int)((const long long*)ei)[i] : ((const int*)ei)[i];
}

// ---------------- kernel 1: zero counters ------------------------------------
__global__ void zero_kernel() {
    int i = blockIdx.x * blockDim.x + threadIdx.x;
    if (i < N_NODES) g_deg[i] = 0;
    if (i < D) { g_sum[i] = 0.f; g_sumsq[i] = 0.f; }
}

// ---------------- kernel 2: count in-degree ----------------------------------
__global__ void count_kernel(const void* __restrict__ ei) {
    int e = blockIdx.x * blockDim.x + threadIdx.x;
    if (e >= N_EDGES) return;
    int is64 = g_is64;
    int dst = load_idx(ei, is64, N_EDGES + e);
    atomicAdd(&g_deg[dst], 1);
}

// ---------------- kernel 3a: per-block degree sums ---------------------------
__global__ __launch_bounds__(SCAN_CHUNK) void scan1_kernel() {
    __shared__ int s[SCAN_CHUNK];
    int t = threadIdx.x;
    int i = blockIdx.x * SCAN_CHUNK + t;
    s[t] = (i < N_NODES) ? g_deg[i] : 0;
    __syncthreads();
#pragma unroll
    for (int off = SCAN_CHUNK / 2; off > 0; off >>= 1) {
        if (t < off) s[t] += s[t + off];
        __syncthreads();
    }
    if (t == 0) g_bsum[blockIdx.x] = s[0];
}

// ---------------- kernel 3b: scan block sums (tiny, 1 block) -----------------
__global__ __launch_bounds__(256) void scan2_kernel() {
    __shared__ int s[256];
    int t = threadIdx.x;
    s[t] = (t < NB_SCAN) ? g_bsum[t] : 0;
    __syncthreads();
    for (int off = 1; off < 256; off <<= 1) {
        int v = (t >= off) ? s[t - off] : 0;
        __syncthreads();
        s[t] += v;
        __syncthreads();
    }
    if (t < NB_SCAN) g_boff[t] = (t == 0) ? 0 : s[t - 1];   // exclusive
}

// ---------------- kernel 3c: per-block exclusive scan + offset ---------------
__global__ __launch_bounds__(SCAN_CHUNK) void scan3_kernel() {
    __shared__ int s[SCAN_CHUNK];
    int t = threadIdx.x;
    int i = blockIdx.x * SCAN_CHUNK + t;
    int v = (i < N_NODES) ? g_deg[i] : 0;
    s[t] = v;
    __syncthreads();
    for (int off = 1; off < SCAN_CHUNK; off <<= 1) {
        int u = (t >= off) ? s[t - off] : 0;
        __syncthreads();
        s[t] += u;
        __syncthreads();
    }
    int incl = s[t];
    int base = g_boff[blockIdx.x];
    if (i < N_NODES) {
        int excl = base + incl - v;
        g_rowptr[i] = excl;
        g_cursor[i] = excl;
        if (i == N_NODES - 1) g_rowptr[N_NODES] = base + incl;
    }
}

// ---------------- kernel 4: fill CSR ------------------------------------------
__global__ void fill_kernel(const void* __restrict__ ei) {
    int e = blockIdx.x * blockDim.x + threadIdx.x;
    if (e >= N_EDGES) return;
    int is64 = g_is64;
    int src = load_idx(ei, is64, e);
    int dst = load_idx(ei, is64, N_EDGES + e);
    int pos = atomicAdd(&g_cursor[dst], 1);
    g_csr[pos] = src;
}

// ---------------- kernel 5: gather + mean (one warp per node) ----------------
__global__ __launch_bounds__(256) void gather_kernel(const float* __restrict__ x) {
    int warp = (blockIdx.x * blockDim.x + threadIdx.x) >> 5;
    int lane = threadIdx.x & 31;
    if (warp >= N_NODES) return;
    int beg = g_rowptr[warp];
    int end = g_rowptr[warp + 1];
    const float4* x4 = (const float4*)x;
    float4 acc = make_float4(0.f, 0.f, 0.f, 0.f);
    float4 acc2 = make_float4(0.f, 0.f, 0.f, 0.f);
    int j = beg;
    for (; j + 1 < end; j += 2) {
        int s0 = g_csr[j];
        int s1 = g_csr[j + 1];
        float4 v0 = __ldg(x4 + (size_t)s0 * (D / 4) + lane);
        float4 v1 = __ldg(x4 + (size_t)s1 * (D / 4) + lane);
        acc.x += v0.x; acc.y += v0.y; acc.z += v0.z; acc.w += v0.w;
        acc2.x += v1.x; acc2.y += v1.y; acc2.z += v1.z; acc2.w += v1.w;
    }
    if (j < end) {
        int s0 = g_csr[j];
        float4 v0 = __ldg(x4 + (size_t)s0 * (D / 4) + lane);
        acc.x += v0.x; acc.y += v0.y; acc.z += v0.z; acc.w += v0.w;
    }
    float inv = 1.0f / (float)max(end - beg, 1);
    acc.x = (acc.x + acc2.x) * inv;
    acc.y = (acc.y + acc2.y) * inv;
    acc.z = (acc.z + acc2.z) * inv;
    acc.w = (acc.w + acc2.w) * inv;
    ((float4*)g_agg)[(size_t)warp * (D / 4) + lane] = acc;
}

// ---------------- kernel 6: fused dual GEMM + BN stats -----------------------
#define BM 128
#define BN_T 128
#define BK 16

__global__ __launch_bounds__(256) void gemm_kernel(const float* __restrict__ x,
                                                   const float* __restrict__ Wl,
                                                   const float* __restrict__ bl,
                                                   const float* __restrict__ Wr) {
    __shared__ float As[BK][BM + 4];
    __shared__ float Bs[BK][BN_T + 4];
    __shared__ float s_sum[BN_T];
    __shared__ float s_sq[BN_T];

    const int tid = threadIdx.x;
    const int tx = tid & 15;
    const int ty = tid >> 4;
    const int blockRow = blockIdx.x * BM;

    float acc[8][8];
#pragma unroll
    for (int i = 0; i < 8; i++)
#pragma unroll
        for (int j = 0; j < 8; j++) acc[i][j] = 0.f;

    const int lr = tid >> 1;
    const int lc = (tid & 1) * 8;

    for (int phase = 0; phase < 2; ++phase) {
        const float* A = phase ? x : (const float*)g_agg;
        const float* W = phase ? Wr : Wl;
        for (int kb = 0; kb < D; kb += BK) {
            {
                int grow = blockRow + lr;
                float4 a0 = make_float4(0.f, 0.f, 0.f, 0.f), a1 = a0;
                if (grow < N_NODES) {
                    const float* ap = A + (size_t)grow * D + kb + lc;
                    a0 = *(const float4*)ap;
                    a1 = *(const float4*)(ap + 4);
                }
                As[lc + 0][lr] = a0.x; As[lc + 1][lr] = a0.y;
                As[lc + 2][lr] = a0.z; As[lc + 3][lr] = a0.w;
                As[lc + 4][lr] = a1.x; As[lc + 5][lr] = a1.y;
                As[lc + 6][lr] = a1.z; As[lc + 7][lr] = a1.w;
            }
            {
                const float* wp = W + lr * D + kb + lc;
                float4 b0 = *(const float4*)wp;
                float4 b1 = *(const float4*)(wp + 4);
                Bs[lc + 0][lr] = b0.x; Bs[lc + 1][lr] = b0.y;
                Bs[lc + 2][lr] = b0.z; Bs[lc + 3][lr] = b0.w;
                Bs[lc + 4][lr] = b1.x; Bs[lc + 5][lr] = b1.y;
                Bs[lc + 6][lr] = b1.z; Bs[lc + 7][lr] = b1.w;
            }
            __syncthreads();
#pragma unroll
            for (int k = 0; k < BK; ++k) {
                float a[8], b[8];
#pragma unroll
                for (int i = 0; i < 8; i++) a[i] = As[k][ty * 8 + i];
                float4 b0 = *(const float4*)&Bs[k][tx * 8];
                float4 b1 = *(const float4*)&Bs[k][tx * 8 + 4];
                b[0] = b0.x; b[1] = b0.y; b[2] = b0.z; b[3] = b0.w;
                b[4] = b1.x; b[5] = b1.y; b[6] = b1.z; b[7] = b1.w;
#pragma unroll
                for (int i = 0; i < 8; i++)
#pragma unroll
                    for (int j = 0; j < 8; j++) acc[i][j] += a[i] * b[j];
            }
            __syncthreads();
        }
    }

    float4 bias0 = *(const float4*)(bl + tx * 8);
    float4 bias1 = *(const float4*)(bl + tx * 8 + 4);
    float bsv[8] = {bias0.x, bias0.y, bias0.z, bias0.w,
                    bias1.x, bias1.y, bias1.z, bias1.w};

    if (tid < BN_T) { s_sum[tid] = 0.f; s_sq[tid] = 0.f; }
    __syncthreads();

    float lsum[8], lsq[8];
#pragma unroll
    for (int j = 0; j < 8; j++) { lsum[j] = 0.f; lsq[j] = 0.f; }

#pragma unroll
    for (int i = 0; i < 8; i++) {
        int row = blockRow + ty * 8 + i;
        if (row < N_NODES) {
            float v[8];
#pragma unroll
            for (int j = 0; j < 8; j++) {
                v[j] = acc[i][j] + bsv[j];
                lsum[j] += v[j];
                lsq[j] += v[j] * v[j];
            }
            float* hp = g_h + (size_t)row * D + tx * 8;
            *(float4*)hp       = make_float4(v[0], v[1], v[2], v[3]);
            *(float4*)(hp + 4) = make_float4(v[4], v[5], v[6], v[7]);
        }
    }
#pragma unroll
    for (int j = 0; j < 8; j++) {
        atomicAdd(&s_sum[tx * 8 + j], lsum[j]);
        atomicAdd(&s_sq[tx * 8 + j], lsq[j]);
    }
    __syncthreads();
    if (tid < BN_T) {
        atomicAdd(&g_sum[tid], s_sum[tid]);
        atomicAdd(&g_sumsq[tid], s_sq[tid]);
    }
}

// ---------------- kernel 7: finalize BN stats --------------------------------
__global__ void stats_kernel(const float* __restrict__ gamma,
                             const float* __restrict__ beta) {
    int c = threadIdx.x;
    if (c >= D) return;
    float s = g_sum[c], ss = g_sumsq[c];
    float inv_n = 1.0f / (float)N_NODES;
    float mu = s * inv_n;
    float var = ss * inv_n - mu * mu;
    float rstd = rsqrtf(var + BN_EPS);
    float sc = gamma[c] * rstd;
    g_scale[c] = sc;
    g_shift[c] = beta[c] - mu * sc;
}

// ---------------- kernel 8: normalize + LeakyReLU ----------------------------
__global__ void norm_kernel(float* __restrict__ out) {
    int i = blockIdx.x * blockDim.x + threadIdx.x;
    if (i >= N_NODES * (D / 4)) return;
    int cb = (i & 31) * 4;
    float4 sc = *(const float4*)&g_scale[cb];
    float4 sh = *(const float4*)&g_shift[cb];
    float4 v = ((float4*)g_h)[i];
    v.x = v.x * sc.x + sh.x;
    v.y = v.y * sc.y + sh.y;
    v.z = v.z * sc.z + sh.z;
    v.w = v.w * sc.w + sh.w;
    v.x = v.x >= 0.f ? v.x : ALPHA * v.x;
    v.y = v.y >= 0.f ? v.y : ALPHA * v.y;
    v.z = v.z >= 0.f ? v.z : ALPHA * v.z;
    v.w = v.w >= 0.f ? v.w : ALPHA * v.w;
    ((float4*)out)[i] = v;
}

// ---------------- launch ------------------------------------------------------
extern "C" void kernel_launch(void* const* d_in, const int* in_sizes, int n_in,
                              void* d_out, int out_size) {
    const float* x     = (const float*)d_in[0];
    const void*  ei    = d_in[1];
    const float* Wl    = (const float*)d_in[2];
    const float* bl    = (const float*)d_in[3];
    const float* Wr    = (const float*)d_in[4];
    const float* gamma = (const float*)d_in[5];
    const float* beta  = (const float*)d_in[6];
    float*       out   = (float*)d_out;

    const int elem4 = N_NODES * (D / 4);

    detect_kernel<<<1, 256>>>((const int*)ei);
    zero_kernel<<<(N_NODES + 255) / 256, 256>>>();
    count_kernel<<<(N_EDGES + 255) / 256, 256>>>(ei);
    scan1_kernel<<<NB_SCAN, SCAN_CHUNK>>>();
    scan2_kernel<<<1, 256>>>();
    scan3_kernel<<<NB_SCAN, SCAN_CHUNK>>>();
    fill_kernel<<<(N_EDGES + 255) / 256, 256>>>(ei);
    gather_kernel<<<(N_NODES * 32 + 255) / 256, 256>>>(x);
    gemm_kernel<<<(N_NODES + BM - 1) / BM, 256>>>(x, Wl, bl, Wr);
    stats_kernel<<<1, 128>>>(gamma, beta);
    norm_kernel<<<(elem4 + 255) / 256, 256>>>(out);
}

// round 6
// speedup vs baseline: 2.2545x; 1.5123x over previous
#include <cuda_runtime.h>

#define N_NODES 100000
#define N_EDGES 1600000
#define D 128
#define ALPHA 0.01f
#define BN_EPS 1e-5f

#define SCAN_CHUNK 512
#define NB_SCAN ((N_NODES + SCAN_CHUNK - 1) / SCAN_CHUNK)   // 196

#define STAT_BLOCKS 400
#define ROWS_PER_STAT ((N_NODES + STAT_BLOCKS - 1) / STAT_BLOCKS)  // 250

// ---------------- scratch (device globals: no allocation allowed) -------------
__device__ int   g_is64;
__device__ int   g_deg[N_NODES];
__device__ int   g_rowptr[N_NODES + 1];
__device__ int   g_cursor[N_NODES];
__device__ int   g_csr[N_EDGES];
__device__ int   g_bsum[NB_SCAN];
__device__ int   g_boff[NB_SCAN];
__device__ float g_agg[(size_t)N_NODES * D];
__device__ float g_h[(size_t)N_NODES * D];
__device__ float g_sum[D];
__device__ float g_sumsq[D];
__device__ float g_scale[D];
__device__ float g_shift[D];

// ---------------- kernel 0: detect edge dtype --------------------------------
__global__ void detect_kernel(const int* __restrict__ ei32) {
    __shared__ int flag;
    if (threadIdx.x == 0) flag = 0;
    __syncthreads();
    int v = ei32[2 * threadIdx.x + 1];
    if (v != 0) flag = 1;
    __syncthreads();
    if (threadIdx.x == 0) g_is64 = (flag == 0) ? 1 : 0;
}

__device__ __forceinline__ int load_idx(const void* ei, int is64, int i) {
    return is64 ? (int)((const long long*)ei)[i] : ((const int*)ei)[i];
}

// ---------------- kernel 1: zero counters ------------------------------------
__global__ void zero_kernel() {
    int i = blockIdx.x * blockDim.x + threadIdx.x;
    if (i < N_NODES) g_deg[i] = 0;
    if (i < D) { g_sum[i] = 0.f; g_sumsq[i] = 0.f; }
}

// ---------------- kernel 2: count in-degree ----------------------------------
__global__ void count_kernel(const void* __restrict__ ei) {
    int e = blockIdx.x * blockDim.x + threadIdx.x;
    if (e >= N_EDGES) return;
    int is64 = g_is64;
    int dst = load_idx(ei, is64, N_EDGES + e);
    atomicAdd(&g_deg[dst], 1);
}

// ---------------- kernel 3a/b/c: multi-block exclusive scan ------------------
__global__ __launch_bounds__(SCAN_CHUNK) void scan1_kernel() {
    __shared__ int s[SCAN_CHUNK];
    int t = threadIdx.x;
    int i = blockIdx.x * SCAN_CHUNK + t;
    s[t] = (i < N_NODES) ? g_deg[i] : 0;
    __syncthreads();
#pragma unroll
    for (int off = SCAN_CHUNK / 2; off > 0; off >>= 1) {
        if (t < off) s[t] += s[t + off];
        __syncthreads();
    }
    if (t == 0) g_bsum[blockIdx.x] = s[0];
}

__global__ __launch_bounds__(256) void scan2_kernel() {
    __shared__ int s[256];
    int t = threadIdx.x;
    s[t] = (t < NB_SCAN) ? g_bsum[t] : 0;
    __syncthreads();
    for (int off = 1; off < 256; off <<= 1) {
        int v = (t >= off) ? s[t - off] : 0;
        __syncthreads();
        s[t] += v;
        __syncthreads();
    }
    if (t < NB_SCAN) g_boff[t] = (t == 0) ? 0 : s[t - 1];
}

__global__ __launch_bounds__(SCAN_CHUNK) void scan3_kernel() {
    __shared__ int s[SCAN_CHUNK];
    int t = threadIdx.x;
    int i = blockIdx.x * SCAN_CHUNK + t;
    int v = (i < N_NODES) ? g_deg[i] : 0;
    s[t] = v;
    __syncthreads();
    for (int off = 1; off < SCAN_CHUNK; off <<= 1) {
        int u = (t >= off) ? s[t - off] : 0;
        __syncthreads();
        s[t] += u;
        __syncthreads();
    }
    int incl = s[t];
    int base = g_boff[blockIdx.x];
    if (i < N_NODES) {
        int excl = base + incl - v;
        g_rowptr[i] = excl;
        g_cursor[i] = excl;
        if (i == N_NODES - 1) g_rowptr[N_NODES] = base + incl;
    }
}

// ---------------- kernel 4: fill CSR ------------------------------------------
__global__ void fill_kernel(const void* __restrict__ ei) {
    int e = blockIdx.x * blockDim.x + threadIdx.x;
    if (e >= N_EDGES) return;
    int is64 = g_is64;
    int src = load_idx(ei, is64, e);
    int dst = load_idx(ei, is64, N_EDGES + e);
    int pos = atomicAdd(&g_cursor[dst], 1);
    g_csr[pos] = src;
}

// ---------------- kernel 5: gather + mean (one warp per node) ----------------
__global__ __launch_bounds__(256) void gather_kernel(const float* __restrict__ x) {
    int warp = (blockIdx.x * blockDim.x + threadIdx.x) >> 5;
    int lane = threadIdx.x & 31;
    if (warp >= N_NODES) return;
    int beg = g_rowptr[warp];
    int end = g_rowptr[warp + 1];
    const float4* x4 = (const float4*)x;
    float4 acc = make_float4(0.f, 0.f, 0.f, 0.f);
    float4 acc2 = make_float4(0.f, 0.f, 0.f, 0.f);
    int j = beg;
    for (; j + 1 < end; j += 2) {
        int s0 = g_csr[j];
        int s1 = g_csr[j + 1];
        float4 v0 = __ldg(x4 + (size_t)s0 * (D / 4) + lane);
        float4 v1 = __ldg(x4 + (size_t)s1 * (D / 4) + lane);
        acc.x += v0.x; acc.y += v0.y; acc.z += v0.z; acc.w += v0.w;
        acc2.x += v1.x; acc2.y += v1.y; acc2.z += v1.z; acc2.w += v1.w;
    }
    if (j < end) {
        int s0 = g_csr[j];
        float4 v0 = __ldg(x4 + (size_t)s0 * (D / 4) + lane);
        acc.x += v0.x; acc.y += v0.y; acc.z += v0.z; acc.w += v0.w;
    }
    float inv = 1.0f / (float)max(end - beg, 1);
    acc.x = (acc.x + acc2.x) * inv;
    acc.y = (acc.y + acc2.y) * inv;
    acc.z = (acc.z + acc2.z) * inv;
    acc.w = (acc.w + acc2.w) * inv;
    ((float4*)g_agg)[(size_t)warp * (D / 4) + lane] = acc;
}

// ---------------- kernel 6: fused dual GEMM (tf32 tensor cores) --------------
// h = mean @ Wl^T + bl + x @ Wr^T
// Block tile 128x128, BK=32, 8 warps (4x2), warp tile 32x64, m16n8k8 atoms.
#define BKT 32
#define PAD 4

__device__ __forceinline__ unsigned f2tf32(float f) {
    unsigned u;
    asm("cvt.rna.tf32.f32 %0, %1;" : "=r"(u) : "f"(f));
    return u;
}

__global__ __launch_bounds__(256) void gemm_kernel(const float* __restrict__ x,
                                                   const float* __restrict__ Wl,
                                                   const float* __restrict__ bl,
                                                   const float* __restrict__ Wr) {
    __shared__ unsigned As[128][BKT + PAD];   // A tile (tf32 bits)
    __shared__ unsigned Bs[128][BKT + PAD];   // W tile (tf32 bits): Bs[n][k]

    const int tid = threadIdx.x;
    const int lane = tid & 31;
    const int wid = tid >> 5;
    const int warp_m = wid >> 1;   // 0..3
    const int warp_n = wid & 1;    // 0..1
    const int blockRow = blockIdx.x * 128;
    const int g = lane >> 2;       // 0..7
    const int t = lane & 3;        // 0..3

    float c[2][8][4];
#pragma unroll
    for (int mi = 0; mi < 2; mi++)
#pragma unroll
        for (int ni = 0; ni < 8; ni++)
#pragma unroll
            for (int r = 0; r < 4; r++) c[mi][ni][r] = 0.f;

    for (int phase = 0; phase < 2; ++phase) {
        const float* A = phase ? x : (const float*)g_agg;
        const float* W = phase ? Wr : Wl;
        for (int kb = 0; kb < D; kb += BKT) {
            // ---- load tiles (each thread: 4 float4 per tile) ----
#pragma unroll
            for (int i = 0; i < 4; i++) {
                int f4 = tid * 4 + i;         // 0..1023
                int row = f4 >> 3;
                int col = (f4 & 7) * 4;
                float4 a = make_float4(0.f, 0.f, 0.f, 0.f);
                if (blockRow + row < N_NODES)
                    a = *(const float4*)(A + (size_t)(blockRow + row) * D + kb + col);
                As[row][col + 0] = f2tf32(a.x);
                As[row][col + 1] = f2tf32(a.y);
                As[row][col + 2] = f2tf32(a.z);
                As[row][col + 3] = f2tf32(a.w);
                float4 w = *(const float4*)(W + (size_t)row * D + kb + col);
                Bs[row][col + 0] = f2tf32(w.x);
                Bs[row][col + 1] = f2tf32(w.y);
                Bs[row][col + 2] = f2tf32(w.z);
                Bs[row][col + 3] = f2tf32(w.w);
            }
            __syncthreads();
            // ---- compute: 4 k-steps of 8 ----
#pragma unroll
            for (int ks = 0; ks < 4; ks++) {
                int k0 = ks * 8;
                unsigned a[2][4];
#pragma unroll
                for (int mi = 0; mi < 2; mi++) {
                    int r = warp_m * 32 + mi * 16 + g;
                    a[mi][0] = As[r][k0 + t];
                    a[mi][1] = As[r + 8][k0 + t];
                    a[mi][2] = As[r][k0 + 4 + t];
                    a[mi][3] = As[r + 8][k0 + 4 + t];
                }
#pragma unroll
                for (int ni = 0; ni < 8; ni++) {
                    int nb = warp_n * 64 + ni * 8 + g;
                    unsigned b0 = Bs[nb][k0 + t];
                    unsigned b1 = Bs[nb][k0 + 4 + t];
#pragma unroll
                    for (int mi = 0; mi < 2; mi++) {
                        asm volatile(
                            "mma.sync.aligned.m16n8k8.row.col.f32.tf32.tf32.f32 "
                            "{%0,%1,%2,%3}, {%4,%5,%6,%7}, {%8,%9}, {%0,%1,%2,%3};"
                            : "+f"(c[mi][ni][0]), "+f"(c[mi][ni][1]),
                              "+f"(c[mi][ni][2]), "+f"(c[mi][ni][3])
                            : "r"(a[mi][0]), "r"(a[mi][1]), "r"(a[mi][2]), "r"(a[mi][3]),
                              "r"(b0), "r"(b1));
                    }
                }
            }
            __syncthreads();
        }
    }

    // ---- epilogue: add bias, store h ----
    float2 bias[8];
#pragma unroll
    for (int ni = 0; ni < 8; ni++)
        bias[ni] = *(const float2*)(bl + warp_n * 64 + ni * 8 + 2 * t);

#pragma unroll
    for (int mi = 0; mi < 2; mi++) {
#pragma unroll
        for (int ro = 0; ro < 2; ro++) {
            int row = blockRow + warp_m * 32 + mi * 16 + ro * 8 + g;
            if (row < N_NODES) {
                float* hp = g_h + (size_t)row * D;
#pragma unroll
                for (int ni = 0; ni < 8; ni++) {
                    int col = warp_n * 64 + ni * 8 + 2 * t;
                    float v0 = c[mi][ni][ro * 2 + 0] + bias[ni].x;
                    float v1 = c[mi][ni][ro * 2 + 1] + bias[ni].y;
                    *(float2*)(hp + col) = make_float2(v0, v1);
                }
            }
        }
    }
}

// ---------------- kernel 6b: per-channel sums over h -------------------------
__global__ __launch_bounds__(256) void statsum_kernel() {
    __shared__ float sh[256], shq[256];
    int tid = threadIdx.x;
    int col = tid & 127;
    int half = tid >> 7;
    int r0 = blockIdx.x * ROWS_PER_STAT;
    int r1 = min(r0 + ROWS_PER_STAT, N_NODES);
    float s = 0.f, q = 0.f;
    for (int r = r0 + half; r < r1; r += 2) {
        float v = g_h[(size_t)r * D + col];
        s += v; q += v * v;
    }
    sh[tid] = s; shq[tid] = q;
    __syncthreads();
    if (tid < 128) {
        float S = sh[tid] + sh[tid + 128];
        float Q = shq[tid] + shq[tid + 128];
        atomicAdd(&g_sum[tid], S);
        atomicAdd(&g_sumsq[tid], Q);
    }
}

// ---------------- kernel 7: finalize BN stats --------------------------------
__global__ void stats_kernel(const float* __restrict__ gamma,
                             const float* __restrict__ beta) {
    int c = threadIdx.x;
    if (c >= D) return;
    float s = g_sum[c], ss = g_sumsq[c];
    float inv_n = 1.0f / (float)N_NODES;
    float mu = s * inv_n;
    float var = ss * inv_n - mu * mu;
    float rstd = rsqrtf(var + BN_EPS);
    float sc = gamma[c] * rstd;
    g_scale[c] = sc;
    g_shift[c] = beta[c] - mu * sc;
}

// ---------------- kernel 8: normalize + LeakyReLU ----------------------------
__global__ void norm_kernel(float* __restrict__ out) {
    int i = blockIdx.x * blockDim.x + threadIdx.x;
    if (i >= N_NODES * (D / 4)) return;
    int cb = (i & 31) * 4;
    float4 sc = *(const float4*)&g_scale[cb];
    float4 sh = *(const float4*)&g_shift[cb];
    float4 v = ((float4*)g_h)[i];
    v.x = v.x * sc.x + sh.x;
    v.y = v.y * sc.y + sh.y;
    v.z = v.z * sc.z + sh.z;
    v.w = v.w * sc.w + sh.w;
    v.x = v.x >= 0.f ? v.x : ALPHA * v.x;
    v.y = v.y >= 0.f ? v.y : ALPHA * v.y;
    v.z = v.z >= 0.f ? v.z : ALPHA * v.z;
    v.w = v.w >= 0.f ? v.w : ALPHA * v.w;
    ((float4*)out)[i] = v;
}

// ---------------- launch ------------------------------------------------------
extern "C" void kernel_launch(void* const* d_in, const int* in_sizes, int n_in,
                              void* d_out, int out_size) {
    const float* x     = (const float*)d_in[0];
    const void*  ei    = d_in[1];
    const float* Wl    = (const float*)d_in[2];
    const float* bl    = (const float*)d_in[3];
    const float* Wr    = (const float*)d_in[4];
    const float* gamma = (const float*)d_in[5];
    const float* beta  = (const float*)d_in[6];
    float*       out   = (float*)d_out;

    const int elem4 = N_NODES * (D / 4);

    detect_kernel<<<1, 256>>>((const int*)ei);
    zero_kernel<<<(N_NODES + 255) / 256, 256>>>();
    count_kernel<<<(N_EDGES + 255) / 256, 256>>>(ei);
    scan1_kernel<<<NB_SCAN, SCAN_CHUNK>>>();
    scan2_kernel<<<1, 256>>>();
    scan3_kernel<<<NB_SCAN, SCAN_CHUNK>>>();
    fill_kernel<<<(N_EDGES + 255) / 256, 256>>>(ei);
    gather_kernel<<<(N_NODES * 32 + 255) / 256, 256>>>(x);
    gemm_kernel<<<(N_NODES + 127) / 128, 256>>>(x, Wl, bl, Wr);
    statsum_kernel<<<STAT_BLOCKS, 256>>>();
    stats_kernel<<<1, 128>>>(gamma, beta);
    norm_kernel<<<(elem4 + 255) / 256, 256>>>(out);
}